// round 1
// baseline (speedup 1.0000x reference)
#include <cuda_runtime.h>
#include <math.h>

// Problem constants
#define CB   8
#define CS   1024
#define CD   1024
#define CH   16
#define CDK  64
#define CDFF 4096

// ---------------------------------------------------------------------------
// Scratch (device globals: allocation-free per harness rules)
// ---------------------------------------------------------------------------
__device__ float g_xn[CB * CS * CD];                 // 32 MB  LN output
__device__ float g_q [CB * CS * CD];                 // 32 MB  [B,S,H,DK]
__device__ float g_k [CB * CS * CD];                 // 32 MB
__device__ float g_v [CB * CS * CD];                 // 32 MB
__device__ float g_o [CB * CS * CD];                 // 32 MB  attn out [B,S,D]
__device__ float g_h1[(size_t)CB * CS * CDFF];       // 128 MB FFN hidden
__device__ float g_sc[(size_t)CB * CH * CS * CS];    // 512 MB scores/probs

// ---------------------------------------------------------------------------
// LayerNorm: matches jnp.std(ddof=1), eps added to std (not var)
// one block of 256 threads per row of 1024
// ---------------------------------------------------------------------------
__global__ __launch_bounds__(256)
void ln_kernel(const float* __restrict__ x,
               const float* __restrict__ gamma,
               const float* __restrict__ beta,
               float* __restrict__ out)
{
    const int row = blockIdx.x;
    const float* xr = x + (size_t)row * CD;
    float* orow = out + (size_t)row * CD;
    const int t = threadIdx.x;

    float v[4];
#pragma unroll
    for (int i = 0; i < 4; i++) v[i] = xr[t + 256 * i];

    __shared__ float red[8];
    __shared__ float s_mean, s_rstd;

    // mean
    float s = v[0] + v[1] + v[2] + v[3];
#pragma unroll
    for (int o = 16; o > 0; o >>= 1) s += __shfl_xor_sync(0xffffffffu, s, o);
    if ((t & 31) == 0) red[t >> 5] = s;
    __syncthreads();
    if (t < 8) {
        float r = red[t];
#pragma unroll
        for (int o = 4; o > 0; o >>= 1) r += __shfl_xor_sync(0xffu, r, o);
        if (t == 0) s_mean = r * (1.0f / CD);
    }
    __syncthreads();
    const float mean = s_mean;

    // unbiased variance
    float q = 0.f;
#pragma unroll
    for (int i = 0; i < 4; i++) { float d = v[i] - mean; q += d * d; }
#pragma unroll
    for (int o = 16; o > 0; o >>= 1) q += __shfl_xor_sync(0xffffffffu, q, o);
    if ((t & 31) == 0) red[t >> 5] = q;
    __syncthreads();
    if (t < 8) {
        float r = red[t];
#pragma unroll
        for (int o = 4; o > 0; o >>= 1) r += __shfl_xor_sync(0xffu, r, o);
        if (t == 0) s_rstd = 1.0f / (sqrtf(r * (1.0f / (CD - 1))) + 1e-5f);
    }
    __syncthreads();
    const float rstd = s_rstd;

#pragma unroll
    for (int i = 0; i < 4; i++) {
        int c = t + 256 * i;
        orow[c] = gamma[c] * (v[i] - mean) * rstd + beta[c];
    }
}

// ---------------------------------------------------------------------------
// Masked softmax over score rows (in-place). 1 block / row, row = 1024.
// ---------------------------------------------------------------------------
__global__ __launch_bounds__(256)
void softmax_kernel(float* __restrict__ scores, const int* __restrict__ mask)
{
    const long row = blockIdx.x;          // (b, h, q) flattened: B*H*S rows
    const int  b   = (int)(row / ((long)CH * CS));
    const int  qi  = (int)(row % CS);
    float* sr = scores + row * (long)CS;
    const int* mr = mask + ((size_t)b * CS + qi) * CS;
    const int t = threadIdx.x;

    __shared__ float red[8];
    __shared__ float s_max, s_inv;

    float v[4];
    float mx = -INFINITY;
#pragma unroll
    for (int i = 0; i < 4; i++) {
        int c = t + 256 * i;
        float s = (mr[c] == 0) ? -1e9f : sr[c];
        v[i] = s;
        mx = fmaxf(mx, s);
    }
#pragma unroll
    for (int o = 16; o > 0; o >>= 1) mx = fmaxf(mx, __shfl_xor_sync(0xffffffffu, mx, o));
    if ((t & 31) == 0) red[t >> 5] = mx;
    __syncthreads();
    if (t < 8) {
        float r = red[t];
#pragma unroll
        for (int o = 4; o > 0; o >>= 1) r = fmaxf(r, __shfl_xor_sync(0xffu, r, o));
        if (t == 0) s_max = r;
    }
    __syncthreads();
    const float m = s_max;

    float sum = 0.f;
#pragma unroll
    for (int i = 0; i < 4; i++) { v[i] = expf(v[i] - m); sum += v[i]; }
#pragma unroll
    for (int o = 16; o > 0; o >>= 1) sum += __shfl_xor_sync(0xffffffffu, sum, o);
    if ((t & 31) == 0) red[t >> 5] = sum;
    __syncthreads();
    if (t < 8) {
        float r = red[t];
#pragma unroll
        for (int o = 4; o > 0; o >>= 1) r += __shfl_xor_sync(0xffu, r, o);
        if (t == 0) s_inv = 1.0f / r;
    }
    __syncthreads();
    const float inv = s_inv;
#pragma unroll
    for (int i = 0; i < 4; i++) sr[t + 256 * i] = v[i] * inv;
}

// ---------------------------------------------------------------------------
// Tiled fp32 GEMM.
//   TRANSB=true : C[m,n] = alpha * sum_k A[m,k] * B[n,k]     (B row-major [N,K])
//   TRANSB=false: C[m,n] = alpha * sum_k A[m,k] * B[k,n]     (B row-major [K,N])
// Batched via blockIdx.z: offset = (z/HH)*s_outer + (z%HH)*s_inner per operand.
// Epilogue: +bias[n] (optional), GELU (compile-time), +res (optional, C-indexed).
// Assumes all dims multiples of tile sizes (true for every call here).
// ---------------------------------------------------------------------------
__device__ __forceinline__ float gelu_f(float x)
{
    const float c = 0.7978845608028654f; // sqrt(2/pi)
    float x3 = x * x * x;
    return 0.5f * x * (1.0f + tanhf(c * (x + 0.044715f * x3)));
}

template <int BM, int BN, int BK, int TM, int TN, bool TRANSB, bool GELU>
__global__ __launch_bounds__((BM / TM) * (BN / TN))
void gemm_kernel(const float* __restrict__ A, int lda, long sAo, long sAi,
                 const float* __restrict__ Bm, int ldb, long sBo, long sBi,
                 float* __restrict__ C, int ldc, long sCo, long sCi,
                 const float* __restrict__ bias,
                 const float* __restrict__ res,
                 float alpha, int K, int HH)
{
    constexpr int THREADS = (BM / TM) * (BN / TN);
    const int z  = blockIdx.z;
    const int zo = z / HH, zi = z % HH;
    A  += (size_t)zo * sAo + (size_t)zi * sAi;
    Bm += (size_t)zo * sBo + (size_t)zi * sBi;
    const size_t cOff = (size_t)zo * sCo + (size_t)zi * sCi;
    C += cOff;
    if (res) res += cOff;

    __shared__ float As[BK][BM];
    __shared__ float Bs[BK][BN];

    const int bm = blockIdx.y * BM;
    const int bn = blockIdx.x * BN;
    const int tid = threadIdx.x;
    const int tx = tid % (BN / TN);
    const int ty = tid / (BN / TN);

    float acc[TM][TN];
#pragma unroll
    for (int i = 0; i < TM; i++)
#pragma unroll
        for (int j = 0; j < TN; j++) acc[i][j] = 0.f;

    for (int k0 = 0; k0 < K; k0 += BK) {
        // A tile [BM x BK] -> As[k][m]
        constexpr int LA = BM * BK / (4 * THREADS);
#pragma unroll
        for (int i = 0; i < LA; i++) {
            int idx = tid + i * THREADS;          // float4 id
            int r   = idx / (BK / 4);
            int c4  = idx % (BK / 4);
            float4 a = *reinterpret_cast<const float4*>(
                A + (size_t)(bm + r) * lda + k0 + c4 * 4);
            As[c4 * 4 + 0][r] = a.x;
            As[c4 * 4 + 1][r] = a.y;
            As[c4 * 4 + 2][r] = a.z;
            As[c4 * 4 + 3][r] = a.w;
        }
        if (TRANSB) {
            // B tile [BN x BK] -> Bs[k][n]
            constexpr int LB = BN * BK / (4 * THREADS);
#pragma unroll
            for (int i = 0; i < LB; i++) {
                int idx = tid + i * THREADS;
                int r   = idx / (BK / 4);
                int c4  = idx % (BK / 4);
                float4 b = *reinterpret_cast<const float4*>(
                    Bm + (size_t)(bn + r) * ldb + k0 + c4 * 4);
                Bs[c4 * 4 + 0][r] = b.x;
                Bs[c4 * 4 + 1][r] = b.y;
                Bs[c4 * 4 + 2][r] = b.z;
                Bs[c4 * 4 + 3][r] = b.w;
            }
        } else {
            // B tile [BK x BN] -> Bs[k][n], already n-contiguous
            constexpr int LB = BK * BN / (4 * THREADS);
#pragma unroll
            for (int i = 0; i < LB; i++) {
                int idx = tid + i * THREADS;
                int r   = idx / (BN / 4);
                int c4  = idx % (BN / 4);
                *reinterpret_cast<float4*>(&Bs[r][c4 * 4]) =
                    *reinterpret_cast<const float4*>(
                        Bm + (size_t)(k0 + r) * ldb + bn + c4 * 4);
            }
        }
        __syncthreads();

#pragma unroll
        for (int k = 0; k < BK; k++) {
            float a[TM], b[TN];
#pragma unroll
            for (int i = 0; i < TM; i++) a[i] = As[k][ty * TM + i];
#pragma unroll
            for (int j = 0; j < TN; j++) b[j] = Bs[k][tx * TN + j];
#pragma unroll
            for (int i = 0; i < TM; i++)
#pragma unroll
                for (int j = 0; j < TN; j++)
                    acc[i][j] = fmaf(a[i], b[j], acc[i][j]);
        }
        __syncthreads();
    }

    // Epilogue: alpha -> +bias -> GELU -> +residual
#pragma unroll
    for (int i = 0; i < TM; i++) {
        int m = bm + ty * TM + i;
#pragma unroll
        for (int j = 0; j < TN; j++) {
            int n = bn + tx * TN + j;
            float v = acc[i][j] * alpha;
            if (bias) v += bias[n];
            if (GELU) v = gelu_f(v);
            if (res)  v += res[(size_t)m * ldc + n];
            C[(size_t)m * ldc + n] = v;
        }
    }
}

// ---------------------------------------------------------------------------
// Launch
// ---------------------------------------------------------------------------
extern "C" void kernel_launch(void* const* d_in, const int* in_sizes, int n_in,
                              void* d_out, int out_size)
{
    const float* x    = (const float*)d_in[0];
    const int*   mask = (const int*)  d_in[1];
    const float* wq   = (const float*)d_in[2];
    const float* bq   = (const float*)d_in[3];
    const float* wk   = (const float*)d_in[4];
    const float* bk   = (const float*)d_in[5];
    const float* wv   = (const float*)d_in[6];
    const float* bv   = (const float*)d_in[7];
    const float* wo   = (const float*)d_in[8];
    const float* bo   = (const float*)d_in[9];
    const float* w1   = (const float*)d_in[10];
    const float* b1   = (const float*)d_in[11];
    const float* w2   = (const float*)d_in[12];
    const float* b2   = (const float*)d_in[13];
    const float* g1   = (const float*)d_in[14];
    const float* be1  = (const float*)d_in[15];
    const float* g2   = (const float*)d_in[16];
    const float* be2  = (const float*)d_in[17];
    float* out = (float*)d_out;

    float *xn, *q, *k, *v, *o, *h1, *sc;
    cudaGetSymbolAddress((void**)&xn, g_xn);
    cudaGetSymbolAddress((void**)&q,  g_q);
    cudaGetSymbolAddress((void**)&k,  g_k);
    cudaGetSymbolAddress((void**)&v,  g_v);
    cudaGetSymbolAddress((void**)&o,  g_o);
    cudaGetSymbolAddress((void**)&h1, g_h1);
    cudaGetSymbolAddress((void**)&sc, g_sc);

    const int M = CB * CS;  // 8192 token rows

    // 1) LN1
    ln_kernel<<<M, 256>>>(x, g1, be1, xn);

    // 2-4) Q,K,V = xn @ W^T + b, kept in [B,S,H,DK] (== [M,D] row-major)
    dim3 gD(CD / 128, M / 128, 1);
    gemm_kernel<128,128,16,8,8,true,false><<<gD, 256>>>(
        xn, CD, 0, 0,  wq, CD, 0, 0,  q, CD, 0, 0,  bq, nullptr, 1.0f, CD, 1);
    gemm_kernel<128,128,16,8,8,true,false><<<gD, 256>>>(
        xn, CD, 0, 0,  wk, CD, 0, 0,  k, CD, 0, 0,  bk, nullptr, 1.0f, CD, 1);
    gemm_kernel<128,128,16,8,8,true,false><<<gD, 256>>>(
        xn, CD, 0, 0,  wv, CD, 0, 0,  v, CD, 0, 0,  bv, nullptr, 1.0f, CD, 1);

    // 5) scores[z] = (1/8) * Q_z @ K_z^T, z over (b,h); operand base = b*S*D + h*DK
    dim3 gS(CS / 128, CS / 128, CB * CH);
    gemm_kernel<128,128,16,8,8,true,false><<<gS, 256>>>(
        q,  CD, (long)CS * CD, CDK,
        k,  CD, (long)CS * CD, CDK,
        sc, CS, (long)CH * CS * CS, (long)CS * CS,
        nullptr, nullptr, 0.125f, CDK, CH);

    // 6) masked softmax in place
    softmax_kernel<<<CB * CH * CS, 256>>>(sc, mask);

    // 7) O_z = P_z @ V_z  (B non-transposed), written straight into [B,S,D]
    dim3 gP(CDK / 64, CS / 128, CB * CH);
    gemm_kernel<128,64,16,8,4,false,false><<<gP, 256>>>(
        sc, CS, (long)CH * CS * CS, (long)CS * CS,
        v,  CD, (long)CS * CD, CDK,
        o,  CD, (long)CS * CD, CDK,
        nullptr, nullptr, 1.0f, CS, CH);

    // 8) x1 = o @ wo^T + bo + x   -> out
    gemm_kernel<128,128,16,8,8,true,false><<<gD, 256>>>(
        o, CD, 0, 0,  wo, CD, 0, 0,  out, CD, 0, 0,  bo, x, 1.0f, CD, 1);

    // 9) LN2
    ln_kernel<<<M, 256>>>(out, g2, be2, xn);

    // 10) h1 = gelu(xn @ w1^T + b1)
    dim3 gF1(CDFF / 128, M / 128, 1);
    gemm_kernel<128,128,16,8,8,true,true><<<gF1, 256>>>(
        xn, CD, 0, 0,  w1, CD, 0, 0,  h1, CDFF, 0, 0,  b1, nullptr, 1.0f, CD, 1);

    // 11) out = x1 + h1 @ w2^T + b2
    gemm_kernel<128,128,16,8,8,true,false><<<gD, 256>>>(
        h1, CDFF, 0, 0,  w2, CDFF, 0, 0,  out, CD, 0, 0,  b2, out, 1.0f, CDFF, 1);
}